// round 6
// baseline (speedup 1.0000x reference)
#include <cuda_runtime.h>
#include <cstdint>

// VoxelHashTable: 2-level hash-grid trilinear interpolation.
// Inputs (metadata order):
//   d_in[0] query_pts (M,3) f32
//   d_in[1] feats0    (n0,32) f32
//   d_in[2] feats1    (n1,32) f32
//   d_in[3] h2v0      (2^20) i32
//   d_in[4] h2v1      (2^20) i32
// Output: (M, 64) f32  — [level0 32 | level1 32]
//
// Warp layout (1 warp = 2 queries):
//   half  = lane>>4        which query of the pair
//   level = (lane>>3)&1    resolution level this lane serves
//   s     = lane&7         channel chunk (floats 4s..4s+3)
// Hash: every lane does ONE lookup for (its query, its level, corner = lane&7).
// Gather: branch-free — invalid corners get weight 0 and read row 0 (exact:
// fmaf(f, 0, acc) == acc). Loads staged in 2 batches of 4 independent LDG.128
// to maximize memory-level parallelism on the L2-hit latency (~250 cyc).
// Each lane's accumulator is exactly output[query*64 + level*32 + 4s..4s+3]:
// the warp store is 512B fully-coalesced STG.128.

#define TSIZE_MASK ((1 << 20) - 1)

// PRIMES % 2^20 (exact):
#define PMX 455773
#define PMY 475301
#define PMZ 655287

__global__ __launch_bounds__(256, 7) void voxel_hash_kernel(
    const float* __restrict__ q,
    const float* __restrict__ f0,
    const float* __restrict__ f1,
    const int* __restrict__ h0,
    const int* __restrict__ h1,
    float* __restrict__ out,
    int M)
{
    const int pair = (blockIdx.x * blockDim.x + threadIdx.x) >> 5;
    const int lane = threadIdx.x & 31;

    const int level = (lane >> 3) & 1;  // this lane's resolution level
    const int s     = lane & 7;         // float4 chunk within the 32-dim feature

    int qidx = pair * 2 + (lane >> 4);
    const bool active = qidx < M;
    if (qidx >= M) qidx = M - 1;        // clamp; store guarded below

    // Per-lane query point (2 distinct rows per warp).
    const float qx = __ldg(q + qidx * 3 + 0);
    const float qy = __ldg(q + qidx * 3 + 1);
    const float qz = __ldg(q + qidx * 3 + 2);

    // This lane's level only. 0.24f == float32(0.12*2.0) exactly.
    const float res = level ? 0.24f : 0.12f;
    const float sx = __fdiv_rn(qx, res);
    const float sy = __fdiv_rn(qy, res);
    const float sz = __fdiv_rn(qz, res);

    const float bx = floorf(sx), by = floorf(sy), bz = floorf(sz);
    const float fx = sx - bx, fy = sy - by, fz = sz - bz;

    // Hash lookup: corner = lane&7 of (this query, this level). All 32 lanes.
    int vidx;
    {
        const int cx = (int)bx + ((lane >> 2) & 1);
        const int cy = (int)by + ((lane >> 1) & 1);
        const int cz = (int)bz + (lane & 1);
        const unsigned hv =
            ((unsigned)(cx * PMX + cy * PMY + cz * PMZ)) & TSIZE_MASK;
        const int* __restrict__ hp = level ? h1 : h0;
        vidx = __ldg(hp + hv);
    }

    const float gx = 1.0f - fx;
    const float gy = 1.0f - fy;
    const float gz = 1.0f - fz;
    const float* __restrict__ fp = (level ? f1 : f0) + s * 4;

    // Source lane base for this (query, level)'s 8 hash results.
    const int src_base = lane & 0x18;   // (half<<4) | (level<<3)

    float4 acc = make_float4(0.f, 0.f, 0.f, 0.f);

    #pragma unroll
    for (int b = 0; b < 2; ++b) {
        // Gather 4 corner indices + weights (branch-free).
        int   v[4];
        float w[4];
        #pragma unroll
        for (int i = 0; i < 4; ++i) {
            const int t = b * 4 + i;
            const int vv = __shfl_sync(0xFFFFFFFFu, vidx, src_base + t);
            // ((wx*wy)*wz) multiply order matches reference prod(axis=2).
            const float ww = ((t & 4) ? fx : gx) *
                             ((t & 2) ? fy : gy) *
                             ((t & 1) ? fz : gz);
            w[i] = (vv >= 0) ? ww : 0.0f;
            v[i] = (vv >= 0) ? vv : 0;
        }

        // 4 independent 128B row loads in flight.
        const float4 r0 = __ldg((const float4*)(fp + (size_t)v[0] * 32));
        const float4 r1 = __ldg((const float4*)(fp + (size_t)v[1] * 32));
        const float4 r2 = __ldg((const float4*)(fp + (size_t)v[2] * 32));
        const float4 r3 = __ldg((const float4*)(fp + (size_t)v[3] * 32));

        acc.x = fmaf(r0.x, w[0], acc.x); acc.y = fmaf(r0.y, w[0], acc.y);
        acc.z = fmaf(r0.z, w[0], acc.z); acc.w = fmaf(r0.w, w[0], acc.w);
        acc.x = fmaf(r1.x, w[1], acc.x); acc.y = fmaf(r1.y, w[1], acc.y);
        acc.z = fmaf(r1.z, w[1], acc.z); acc.w = fmaf(r1.w, w[1], acc.w);
        acc.x = fmaf(r2.x, w[2], acc.x); acc.y = fmaf(r2.y, w[2], acc.y);
        acc.z = fmaf(r2.z, w[2], acc.z); acc.w = fmaf(r2.w, w[2], acc.w);
        acc.x = fmaf(r3.x, w[3], acc.x); acc.y = fmaf(r3.y, w[3], acc.y);
        acc.z = fmaf(r3.z, w[3], acc.z); acc.w = fmaf(r3.w, w[3], acc.w);
    }

    // Each lane writes its own (query, level, chunk): 512B contiguous per warp.
    if (active) {
        *(float4*)(out + (size_t)qidx * 64 + level * 32 + s * 4) = acc;
    }
}

extern "C" void kernel_launch(void* const* d_in, const int* in_sizes, int n_in,
                              void* d_out, int out_size)
{
    const float* q  = (const float*)d_in[0];
    const float* f0 = (const float*)d_in[1];
    const float* f1 = (const float*)d_in[2];
    const int*   h0 = (const int*)d_in[3];
    const int*   h1 = (const int*)d_in[4];
    float* out = (float*)d_out;

    const int M = in_sizes[0] / 3;
    const int pairs = (M + 1) / 2;

    const int warps_per_block = 8;
    const int blocks = (pairs + warps_per_block - 1) / warps_per_block;
    voxel_hash_kernel<<<blocks, warps_per_block * 32>>>(q, f0, f1, h0, h1, out, M);
}